// round 1
// baseline (speedup 1.0000x reference)
#include <cuda_runtime.h>

// Problem dims (fixed by the reference)
#define QN   512
#define CN   512
#define TNT  128
#define DIN  512
#define DHD  256
#define KCORR (TNT * DHD)   // 32768
#define MAXLAG 4
#define NLAG  9             // lags -4..4

// ---------------------------------------------------------------------------
// Scratch (static device globals; no allocation allowed)
// ---------------------------------------------------------------------------
__device__ float g_H [QN * TNT * DHD];  // 64 MB  hidden activations (reused)
__device__ float g_A [QN * TNT * DHD];  // 64 MB  audio features  [Q,T,DH]
__device__ float g_PV[CN * TNT * DHD];  // 64 MB  projected video [C,T,DH]
__device__ float g_Wc[DHD * DHD];       // folded v_w2 @ W
__device__ float g_bc[DHD];             // folded v_b2 @ W
__device__ float g_S [NLAG * QN * CN];  // 9.4 MB per-lag scores

// ---------------------------------------------------------------------------
// Kernel 0: fold video second-layer weights through W
//   Wc = v_w2 @ W   (256x256),  bc = v_b2 @ W
// ---------------------------------------------------------------------------
__global__ void prep_w_kernel(const float* __restrict__ v_w2,
                              const float* __restrict__ v_b2,
                              const float* __restrict__ W) {
    int i = blockIdx.x;   // row of Wc
    int j = threadIdx.x;  // col
    float acc = 0.f;
    #pragma unroll 8
    for (int k = 0; k < DHD; ++k)
        acc += v_w2[i * DHD + k] * W[k * DHD + j];
    g_Wc[i * DHD + j] = acc;
    if (i == 0) {
        float accb = 0.f;
        #pragma unroll 8
        for (int k = 0; k < DHD; ++k)
            accb += v_b2[k] * W[k * DHD + j];
        g_bc[j] = accb;
    }
}

// ---------------------------------------------------------------------------
// Generic NN GEMM:  C[M,N] = (relu?)(A[M,K] @ B[K,N] + bias[N])
// 128x128 tile, BK=16, 256 threads, 8x8 per-thread register tile.
// ---------------------------------------------------------------------------
template <bool RELU>
__global__ __launch_bounds__(256)
void gemm_nn_kernel(const float* __restrict__ A,
                    const float* __restrict__ B,
                    const float* __restrict__ bias,
                    float* __restrict__ Cout,
                    int M, int K, int N) {
    const int BM = 128, BN = 128, BK = 16;
    __shared__ float As[BK][BM];
    __shared__ float Bs[BK][BN];

    const int tid = threadIdx.x;
    const int bm = blockIdx.x * BM;
    const int bn = blockIdx.y * BN;

    const int tm = (tid / 16) * 4;   // 0..60
    const int tn = (tid % 16) * 4;   // 0..60

    // A load mapping: 2x float4, rows aRow & aRow+64, cols aCol..aCol+3 (of BK)
    const int aRow = tid / 4;          // 0..63
    const int aCol = (tid % 4) * 4;    // 0,4,8,12
    // B load mapping: 2x float4, k-rows bRow & bRow+8, cols bCol..bCol+3
    const int bRow = tid / 32;         // 0..7
    const int bCol = (tid % 32) * 4;   // 0..124

    float acc[8][8];
    #pragma unroll
    for (int i = 0; i < 8; ++i)
        #pragma unroll
        for (int j = 0; j < 8; ++j) acc[i][j] = 0.f;

    for (int k0 = 0; k0 < K; k0 += BK) {
        // Load A tile, store transposed As[k][m]
        #pragma unroll
        for (int h = 0; h < 2; ++h) {
            int m = aRow + h * 64;
            float4 v = *(const float4*)&A[(size_t)(bm + m) * K + k0 + aCol];
            As[aCol + 0][m] = v.x;
            As[aCol + 1][m] = v.y;
            As[aCol + 2][m] = v.z;
            As[aCol + 3][m] = v.w;
        }
        // Load B tile directly Bs[k][n]
        #pragma unroll
        for (int h = 0; h < 2; ++h) {
            int kr = bRow + h * 8;
            float4 v = *(const float4*)&B[(size_t)(k0 + kr) * N + bn + bCol];
            *(float4*)&Bs[kr][bCol] = v;
        }
        __syncthreads();

        #pragma unroll
        for (int k = 0; k < BK; ++k) {
            float4 a0 = *(const float4*)&As[k][tm];
            float4 a1 = *(const float4*)&As[k][64 + tm];
            float4 b0 = *(const float4*)&Bs[k][tn];
            float4 b1 = *(const float4*)&Bs[k][64 + tn];
            float af[8] = {a0.x, a0.y, a0.z, a0.w, a1.x, a1.y, a1.z, a1.w};
            float bf[8] = {b0.x, b0.y, b0.z, b0.w, b1.x, b1.y, b1.z, b1.w};
            #pragma unroll
            for (int i = 0; i < 8; ++i)
                #pragma unroll
                for (int j = 0; j < 8; ++j)
                    acc[i][j] += af[i] * bf[j];
        }
        __syncthreads();
    }

    // Epilogue: bias (+relu), vectorized store
    #pragma unroll
    for (int i = 0; i < 8; ++i) {
        int r = bm + ((i < 4) ? (tm + i) : (64 + tm + (i - 4)));
        #pragma unroll
        for (int half = 0; half < 2; ++half) {
            int cbase = bn + half * 64 + tn;
            float4 o;
            o.x = acc[i][half * 4 + 0] + bias[cbase + 0];
            o.y = acc[i][half * 4 + 1] + bias[cbase + 1];
            o.z = acc[i][half * 4 + 2] + bias[cbase + 2];
            o.w = acc[i][half * 4 + 3] + bias[cbase + 3];
            if (RELU) {
                o.x = fmaxf(o.x, 0.f); o.y = fmaxf(o.y, 0.f);
                o.z = fmaxf(o.z, 0.f); o.w = fmaxf(o.w, 0.f);
            }
            *(float4*)&Cout[(size_t)r * N + cbase] = o;
        }
    }
}

// ---------------------------------------------------------------------------
// Correlation: for each lag j in [-4,4]:
//   S_j[q,c] = sum_{t,d} A[q,t,d] * PV[c,(t+j) mod T, d]
// NT-layout GEMM over K = T*DH with per-chunk circular time shift on PV.
// grid: (Q/128, C/128, 9)
// ---------------------------------------------------------------------------
__global__ __launch_bounds__(256)
void corr_kernel() {
    const int BM = 128, BN = 128, BK = 16;
    __shared__ float As[BK][BM];
    __shared__ float Bs[BK][BN];

    const int tid = threadIdx.x;
    const int bm = blockIdx.x * BM;            // q tile
    const int bn = blockIdx.y * BN;            // c tile
    const int lag = (int)blockIdx.z - MAXLAG;  // -4..4

    const int tm = (tid / 16) * 4;
    const int tn = (tid % 16) * 4;
    const int ldRow = tid / 4;          // 0..63
    const int ldCol = (tid % 4) * 4;    // 0,4,8,12

    float acc[8][8];
    #pragma unroll
    for (int i = 0; i < 8; ++i)
        #pragma unroll
        for (int j = 0; j < 8; ++j) acc[i][j] = 0.f;

    for (int k0 = 0; k0 < KCORR; k0 += BK) {
        int t  = k0 >> 8;                       // /DHD (=256)
        int d0 = k0 & (DHD - 1);
        int ts = t + lag;
        ts = (ts + TNT) & (TNT - 1);            // circular shift (T=128 pow2)
        int kb = ts * DHD + d0;                 // shifted K base for PV

        // A tile (q rows), transpose into As[k][m]
        #pragma unroll
        for (int h = 0; h < 2; ++h) {
            int m = ldRow + h * 64;
            float4 v = *(const float4*)&g_A[(size_t)(bm + m) * KCORR + k0 + ldCol];
            As[ldCol + 0][m] = v.x;
            As[ldCol + 1][m] = v.y;
            As[ldCol + 2][m] = v.z;
            As[ldCol + 3][m] = v.w;
        }
        // PV tile (c rows) with shifted K base, transpose into Bs[k][n]
        #pragma unroll
        for (int h = 0; h < 2; ++h) {
            int n = ldRow + h * 64;
            float4 v = *(const float4*)&g_PV[(size_t)(bn + n) * KCORR + kb + ldCol];
            Bs[ldCol + 0][n] = v.x;
            Bs[ldCol + 1][n] = v.y;
            Bs[ldCol + 2][n] = v.z;
            Bs[ldCol + 3][n] = v.w;
        }
        __syncthreads();

        #pragma unroll
        for (int k = 0; k < BK; ++k) {
            float4 a0 = *(const float4*)&As[k][tm];
            float4 a1 = *(const float4*)&As[k][64 + tm];
            float4 b0 = *(const float4*)&Bs[k][tn];
            float4 b1 = *(const float4*)&Bs[k][64 + tn];
            float af[8] = {a0.x, a0.y, a0.z, a0.w, a1.x, a1.y, a1.z, a1.w};
            float bf[8] = {b0.x, b0.y, b0.z, b0.w, b1.x, b1.y, b1.z, b1.w};
            #pragma unroll
            for (int i = 0; i < 8; ++i)
                #pragma unroll
                for (int j = 0; j < 8; ++j)
                    acc[i][j] += af[i] * bf[j];
        }
        __syncthreads();
    }

    float* Sz = g_S + (size_t)blockIdx.z * QN * CN;
    #pragma unroll
    for (int i = 0; i < 8; ++i) {
        int r = bm + ((i < 4) ? (tm + i) : (64 + tm + (i - 4)));
        #pragma unroll
        for (int half = 0; half < 2; ++half) {
            int cbase = bn + half * 64 + tn;
            float4 o;
            o.x = acc[i][half * 4 + 0];
            o.y = acc[i][half * 4 + 1];
            o.z = acc[i][half * 4 + 2];
            o.w = acc[i][half * 4 + 3];
            *(float4*)&Sz[(size_t)r * CN + cbase] = o;
        }
    }
}

// ---------------------------------------------------------------------------
// Final max over lags
// ---------------------------------------------------------------------------
__global__ void maxlag_kernel(float* __restrict__ out) {
    int idx = blockIdx.x * blockDim.x + threadIdx.x;  // 0..QN*CN-1
    float m = g_S[idx];
    #pragma unroll
    for (int j = 1; j < NLAG; ++j)
        m = fmaxf(m, g_S[(size_t)j * QN * CN + idx]);
    out[idx] = m;
}

// ---------------------------------------------------------------------------
// Launch
// ---------------------------------------------------------------------------
extern "C" void kernel_launch(void* const* d_in, const int* in_sizes, int n_in,
                              void* d_out, int out_size) {
    const float* audio = (const float*)d_in[0];
    const float* video = (const float*)d_in[1];
    const float* a_w1  = (const float*)d_in[2];
    const float* a_b1  = (const float*)d_in[3];
    const float* a_w2  = (const float*)d_in[4];
    const float* a_b2  = (const float*)d_in[5];
    const float* v_w1  = (const float*)d_in[6];
    const float* v_b1  = (const float*)d_in[7];
    const float* v_w2  = (const float*)d_in[8];
    const float* v_b2  = (const float*)d_in[9];
    const float* W     = (const float*)d_in[10];
    // d_in[11] = max_lag, fixed at 4 for this problem (compile-time MAXLAG)
    float* out = (float*)d_out;

    float *gH, *gA, *gPV, *gWc, *gbc;
    cudaGetSymbolAddress((void**)&gH,  g_H);
    cudaGetSymbolAddress((void**)&gA,  g_A);
    cudaGetSymbolAddress((void**)&gPV, g_PV);
    cudaGetSymbolAddress((void**)&gWc, g_Wc);
    cudaGetSymbolAddress((void**)&gbc, g_bc);

    const int ROWS = QN * TNT;  // 65536 (same for audio and video)

    // 0) fold v_w2 @ W
    prep_w_kernel<<<DHD, DHD>>>(v_w2, v_b2, W);

    // 1) audio MLP: H = relu(audio @ a_w1 + a_b1); A = H @ a_w2 + a_b2
    gemm_nn_kernel<true ><<<dim3(ROWS / 128, DHD / 128), 256>>>(
        audio, a_w1, a_b1, gH, ROWS, DIN, DHD);
    gemm_nn_kernel<false><<<dim3(ROWS / 128, DHD / 128), 256>>>(
        gH, a_w2, a_b2, gA, ROWS, DHD, DHD);

    // 2) video MLP with folded projection: PV = relu(video @ v_w1 + v_b1) @ Wc + bc
    gemm_nn_kernel<true ><<<dim3(ROWS / 128, DHD / 128), 256>>>(
        video, v_w1, v_b1, gH, ROWS, DIN, DHD);
    gemm_nn_kernel<false><<<dim3(ROWS / 128, DHD / 128), 256>>>(
        gH, gWc, gbc, gPV, ROWS, DHD, DHD);

    // 3) per-lag correlation GEMMs (one wave: 4*4*9 = 144 CTAs)
    corr_kernel<<<dim3(QN / 128, CN / 128, NLAG), 256>>>();

    // 4) max over lags
    maxlag_kernel<<<(QN * CN) / 256, 256>>>(out);
}

// round 3
// speedup vs baseline: 2.0585x; 2.0585x over previous
#include <cuda_runtime.h>
#include <cuda_bf16.h>
#include <cstdint>

// Problem dims (fixed by the reference)
#define QN   512
#define CN   512
#define TNT  128
#define DIN  512
#define DHD  256
#define KCORR (TNT * DHD)   // 32768
#define MAXLAG 4
#define NLAG  9             // lags -4..4

// ---------------------------------------------------------------------------
// Scratch (static device globals; no allocation allowed)
// ---------------------------------------------------------------------------
__device__ float g_H [QN * TNT * DHD];          // 64 MB hidden activations (reused)
__device__ __nv_bfloat16 g_Ah[QN * TNT * DHD];  // audio features hi  [Q, T*DH]
__device__ __nv_bfloat16 g_Al[QN * TNT * DHD];  // audio features lo
__device__ __nv_bfloat16 g_Ph[CN * TNT * DHD];  // projected video hi [C, T*DH]
__device__ __nv_bfloat16 g_Pl[CN * TNT * DHD];  // projected video lo
__device__ float g_Wc[DHD * DHD];               // folded v_w2 @ W
__device__ float g_bc[DHD];                     // folded v_b2 @ W
__device__ float g_S [NLAG * QN * CN];          // per-lag scores

// ---------------------------------------------------------------------------
// Portable PTX helpers (all valid on compute_103 virtual target)
// ---------------------------------------------------------------------------
__device__ __forceinline__ uint32_t smem_u32(const void* p) {
    uint32_t a;
    asm("{ .reg .u64 t; cvta.to.shared.u64 t, %1; cvt.u32.u64 %0, t; }"
        : "=r"(a) : "l"(p));
    return a;
}

#define CP_ASYNC_16(dst, src) \
    asm volatile("cp.async.ca.shared.global [%0], [%1], 16;" \
        :: "r"(dst), "l"(src) : "memory")
#define CP_ASYNC_COMMIT() asm volatile("cp.async.commit_group;" ::: "memory")
#define CP_ASYNC_WAIT_1() asm volatile("cp.async.wait_group 1;" ::: "memory")
#define CP_ASYNC_WAIT_0() asm volatile("cp.async.wait_group 0;" ::: "memory")

#define LDSM_X4(r, addr) \
    asm volatile("ldmatrix.sync.aligned.m8n8.x4.shared.b16 {%0,%1,%2,%3}, [%4];" \
        : "=r"((r)[0]), "=r"((r)[1]), "=r"((r)[2]), "=r"((r)[3]) : "r"(addr))

__device__ __forceinline__ void mma16816(float* c, const uint32_t* a,
                                         const uint32_t* b) {
    asm volatile(
        "mma.sync.aligned.m16n8k16.row.col.f32.bf16.bf16.f32 "
        "{%0,%1,%2,%3}, {%4,%5,%6,%7}, {%8,%9}, {%0,%1,%2,%3};"
        : "+f"(c[0]), "+f"(c[1]), "+f"(c[2]), "+f"(c[3])
        : "r"(a[0]), "r"(a[1]), "r"(a[2]), "r"(a[3]), "r"(b[0]), "r"(b[1]));
}

// ---------------------------------------------------------------------------
// Kernel 0: fold video second-layer weights through W
// ---------------------------------------------------------------------------
__global__ void prep_w_kernel(const float* __restrict__ v_w2,
                              const float* __restrict__ v_b2,
                              const float* __restrict__ W) {
    int i = blockIdx.x;
    int j = threadIdx.x;
    float acc = 0.f;
    #pragma unroll 8
    for (int k = 0; k < DHD; ++k)
        acc += v_w2[i * DHD + k] * W[k * DHD + j];
    g_Wc[i * DHD + j] = acc;
    if (i == 0) {
        float accb = 0.f;
        #pragma unroll 8
        for (int k = 0; k < DHD; ++k)
            accb += v_b2[k] * W[k * DHD + j];
        g_bc[j] = accb;
    }
}

// ---------------------------------------------------------------------------
// NN GEMM (SIMT fp32):  C = (relu?)(A @ B + bias); SPLIT writes bf16 hi/lo.
// ---------------------------------------------------------------------------
template <bool RELU, bool SPLIT>
__global__ __launch_bounds__(256)
void gemm_nn_kernel(const float* __restrict__ A,
                    const float* __restrict__ B,
                    const float* __restrict__ bias,
                    float* __restrict__ Cout,
                    __nv_bfloat16* __restrict__ Chi,
                    __nv_bfloat16* __restrict__ Clo,
                    int M, int K, int N) {
    const int BM = 128, BN = 128, BK = 16;
    __shared__ float As[BK][BM];
    __shared__ float Bs[BK][BN];

    const int tid = threadIdx.x;
    const int bm = blockIdx.x * BM;
    const int bn = blockIdx.y * BN;

    const int tm = (tid / 16) * 4;
    const int tn = (tid % 16) * 4;
    const int aRow = tid / 4;
    const int aCol = (tid % 4) * 4;
    const int bRow = tid / 32;
    const int bCol = (tid % 32) * 4;

    float acc[8][8];
    #pragma unroll
    for (int i = 0; i < 8; ++i)
        #pragma unroll
        for (int j = 0; j < 8; ++j) acc[i][j] = 0.f;

    for (int k0 = 0; k0 < K; k0 += BK) {
        #pragma unroll
        for (int h = 0; h < 2; ++h) {
            int m = aRow + h * 64;
            float4 v = *(const float4*)&A[(size_t)(bm + m) * K + k0 + aCol];
            As[aCol + 0][m] = v.x;
            As[aCol + 1][m] = v.y;
            As[aCol + 2][m] = v.z;
            As[aCol + 3][m] = v.w;
        }
        #pragma unroll
        for (int h = 0; h < 2; ++h) {
            int kr = bRow + h * 8;
            float4 v = *(const float4*)&B[(size_t)(k0 + kr) * N + bn + bCol];
            *(float4*)&Bs[kr][bCol] = v;
        }
        __syncthreads();

        #pragma unroll
        for (int k = 0; k < BK; ++k) {
            float4 a0 = *(const float4*)&As[k][tm];
            float4 a1 = *(const float4*)&As[k][64 + tm];
            float4 b0 = *(const float4*)&Bs[k][tn];
            float4 b1 = *(const float4*)&Bs[k][64 + tn];
            float af[8] = {a0.x, a0.y, a0.z, a0.w, a1.x, a1.y, a1.z, a1.w};
            float bf[8] = {b0.x, b0.y, b0.z, b0.w, b1.x, b1.y, b1.z, b1.w};
            #pragma unroll
            for (int i = 0; i < 8; ++i)
                #pragma unroll
                for (int j = 0; j < 8; ++j)
                    acc[i][j] += af[i] * bf[j];
        }
        __syncthreads();
    }

    #pragma unroll
    for (int i = 0; i < 8; ++i) {
        int r = bm + ((i < 4) ? (tm + i) : (64 + tm + (i - 4)));
        #pragma unroll
        for (int half = 0; half < 2; ++half) {
            int cbase = bn + half * 64 + tn;
            float o[4];
            #pragma unroll
            for (int j = 0; j < 4; ++j) {
                o[j] = acc[i][half * 4 + j] + bias[cbase + j];
                if (RELU) o[j] = fmaxf(o[j], 0.f);
            }
            if (SPLIT) {
                __nv_bfloat16 h[4], l[4];
                #pragma unroll
                for (int j = 0; j < 4; ++j) {
                    h[j] = __float2bfloat16(o[j]);
                    l[j] = __float2bfloat16(o[j] - __bfloat162float(h[j]));
                }
                __nv_bfloat162* ph = (__nv_bfloat162*)&Chi[(size_t)r * N + cbase];
                __nv_bfloat162* pl = (__nv_bfloat162*)&Clo[(size_t)r * N + cbase];
                ph[0] = __nv_bfloat162(h[0], h[1]);
                ph[1] = __nv_bfloat162(h[2], h[3]);
                pl[0] = __nv_bfloat162(l[0], l[1]);
                pl[1] = __nv_bfloat162(l[2], l[3]);
            } else {
                float4 v = {o[0], o[1], o[2], o[3]};
                *(float4*)&Cout[(size_t)r * N + cbase] = v;
            }
        }
    }
}

// ---------------------------------------------------------------------------
// Correlation on HMMA (mma.sync bf16, split hi/lo):
//   one CTA per (q-tile 128, c-tile 128, lag); 8 warps, warp tile 64x32.
//   K chunks of 32 bf16; SMEM rows padded to 80 B (conflict-free ldmatrix).
//   cp.async double buffering.
// ---------------------------------------------------------------------------
#define BKC     32                  // K elems per chunk
#define NCHUNK  (KCORR / BKC)       // 1024
#define ROWB    80                  // padded row stride in bytes (64 data + 16)
#define TILE_PB (128 * ROWB)        // 10240
#define BUF_PB  (4 * TILE_PB)       // Ah, Al, Ph, Pl = 40960
#define CORR_SMEM (2 * BUF_PB)      // 81920

extern __shared__ char dsm[];

// issue cp.async for one chunk into buffer `buf`
__device__ __forceinline__ void corr_prefetch(
    uint32_t sb, int buf, int c, int bm, int bn, int lag,
    const __nv_bfloat16* __restrict__ Ah, const __nv_bfloat16* __restrict__ Al,
    const __nv_bfloat16* __restrict__ Ph, const __nv_bfloat16* __restrict__ Pl,
    int tid)
{
    const int k0 = c * BKC;
    const int t  = c >> 3;                       // k0 / 256
    const int d0 = (c & 7) << 5;                 // k0 % 256
    const int ts = (t + lag + TNT) & (TNT - 1);
    const int kb = ts * DHD + d0;

    const uint32_t base = sb + buf * BUF_PB;
    #pragma unroll
    for (int i = 0; i < 8; ++i) {
        int u    = tid + i * 256;                // 0..2047
        int tile = u >> 9;                       // 0..3
        int w    = u & 511;
        int row  = w >> 2;
        int seg  = w & 3;                        // 16B segment within 64B row
        uint32_t dst = base + tile * TILE_PB + row * ROWB + seg * 16;
        const __nv_bfloat16* src;
        if (tile == 0)      src = Ah + (size_t)(bm + row) * KCORR + k0 + seg * 8;
        else if (tile == 1) src = Al + (size_t)(bm + row) * KCORR + k0 + seg * 8;
        else if (tile == 2) src = Ph + (size_t)(bn + row) * KCORR + kb + seg * 8;
        else                src = Pl + (size_t)(bn + row) * KCORR + kb + seg * 8;
        CP_ASYNC_16(dst, src);
    }
    CP_ASYNC_COMMIT();
}

__global__ __launch_bounds__(256, 1)
void corr_hmma_kernel(const __nv_bfloat16* __restrict__ Ah,
                      const __nv_bfloat16* __restrict__ Al,
                      const __nv_bfloat16* __restrict__ Ph,
                      const __nv_bfloat16* __restrict__ Pl) {
    const uint32_t sb = smem_u32(dsm);
    const int tid  = threadIdx.x;
    const int wid  = tid >> 5;
    const int lane = tid & 31;
    const int bm = blockIdx.x * 128;           // q tile
    const int bn = blockIdx.y * 128;           // c tile
    const int lag = (int)blockIdx.z - MAXLAG;

    const int wm = (wid >> 2) * 64;            // warp m offset (0, 64)
    const int wn = (wid & 3) * 32;             // warp n offset (0,32,64,96)

    float acc[4][4][4];                         // [mi][nf][reg]
    #pragma unroll
    for (int mi = 0; mi < 4; ++mi)
        #pragma unroll
        for (int nf = 0; nf < 4; ++nf)
            #pragma unroll
            for (int r = 0; r < 4; ++r) acc[mi][nf][r] = 0.f;

    // ldmatrix lane addressing (constant across chunks)
    const int aRow = wm + (lane & 15);
    const int aSeg = (lane >> 4) << 4;          // 0 or 16 bytes (k or k+8)
    const int bg   = lane >> 3;                 // 0..3
    const int bRow = wn + ((bg >> 1) << 3) + (lane & 7);
    const int bSeg = (bg & 1) << 4;

    corr_prefetch(sb, 0, 0, bm, bn, lag, Ah, Al, Ph, Pl, tid);

    for (int c = 0; c < NCHUNK; ++c) {
        const int buf = c & 1;
        if (c + 1 < NCHUNK) {
            corr_prefetch(sb, buf ^ 1, c + 1, bm, bn, lag, Ah, Al, Ph, Pl, tid);
            CP_ASYNC_WAIT_1();
        } else {
            CP_ASYNC_WAIT_0();
        }
        __syncthreads();

        const uint32_t tb  = sb + buf * BUF_PB;
        const uint32_t ahB = tb + 0 * TILE_PB;
        const uint32_t alB = tb + 1 * TILE_PB;
        const uint32_t phB = tb + 2 * TILE_PB;
        const uint32_t plB = tb + 3 * TILE_PB;

        #pragma unroll
        for (int ks = 0; ks < 2; ++ks) {
            const int kbyte = ks * 32;
            uint32_t ah[4][4], al[4][4], ph[4][2], pl[4][2];
            #pragma unroll
            for (int mi = 0; mi < 4; ++mi) {
                uint32_t off = (uint32_t)(aRow + mi * 16) * ROWB + kbyte + aSeg;
                LDSM_X4(ah[mi], ahB + off);
                LDSM_X4(al[mi], alB + off);
            }
            #pragma unroll
            for (int ni = 0; ni < 2; ++ni) {
                uint32_t off = (uint32_t)(bRow + ni * 16) * ROWB + kbyte + bSeg;
                uint32_t r[4];
                LDSM_X4(r, phB + off);
                ph[2 * ni][0] = r[0]; ph[2 * ni][1] = r[1];
                ph[2 * ni + 1][0] = r[2]; ph[2 * ni + 1][1] = r[3];
                LDSM_X4(r, plB + off);
                pl[2 * ni][0] = r[0]; pl[2 * ni][1] = r[1];
                pl[2 * ni + 1][0] = r[2]; pl[2 * ni + 1][1] = r[3];
            }
            #pragma unroll
            for (int mi = 0; mi < 4; ++mi)
                #pragma unroll
                for (int nf = 0; nf < 4; ++nf) {
                    mma16816(acc[mi][nf], ah[mi], ph[nf]);  // hi*hi
                    mma16816(acc[mi][nf], ah[mi], pl[nf]);  // hi*lo
                    mma16816(acc[mi][nf], al[mi], ph[nf]);  // lo*hi
                }
        }
        __syncthreads();
    }

    // Epilogue: fragment layout -> g_S
    float* Sz = g_S + (size_t)blockIdx.z * QN * CN;
    #pragma unroll
    for (int mi = 0; mi < 4; ++mi) {
        int r0 = bm + wm + mi * 16 + (lane >> 2);
        #pragma unroll
        for (int nf = 0; nf < 4; ++nf) {
            int col = bn + wn + nf * 8 + 2 * (lane & 3);
            float2 v0 = {acc[mi][nf][0], acc[mi][nf][1]};
            float2 v1 = {acc[mi][nf][2], acc[mi][nf][3]};
            *(float2*)&Sz[(size_t)r0 * CN + col]       = v0;
            *(float2*)&Sz[(size_t)(r0 + 8) * CN + col] = v1;
        }
    }
}

// ---------------------------------------------------------------------------
// Final max over lags
// ---------------------------------------------------------------------------
__global__ void maxlag_kernel(float* __restrict__ out) {
    int idx = blockIdx.x * blockDim.x + threadIdx.x;
    float m = g_S[idx];
    #pragma unroll
    for (int j = 1; j < NLAG; ++j)
        m = fmaxf(m, g_S[(size_t)j * QN * CN + idx]);
    out[idx] = m;
}

// ---------------------------------------------------------------------------
// Launch
// ---------------------------------------------------------------------------
extern "C" void kernel_launch(void* const* d_in, const int* in_sizes, int n_in,
                              void* d_out, int out_size) {
    const float* audio = (const float*)d_in[0];
    const float* video = (const float*)d_in[1];
    const float* a_w1  = (const float*)d_in[2];
    const float* a_b1  = (const float*)d_in[3];
    const float* a_w2  = (const float*)d_in[4];
    const float* a_b2  = (const float*)d_in[5];
    const float* v_w1  = (const float*)d_in[6];
    const float* v_b1  = (const float*)d_in[7];
    const float* v_w2  = (const float*)d_in[8];
    const float* v_b2  = (const float*)d_in[9];
    const float* W     = (const float*)d_in[10];
    float* out = (float*)d_out;

    float *gH, *gWc, *gbc;
    __nv_bfloat16 *gAh, *gAl, *gPh, *gPl;
    cudaGetSymbolAddress((void**)&gH,  g_H);
    cudaGetSymbolAddress((void**)&gAh, g_Ah);
    cudaGetSymbolAddress((void**)&gAl, g_Al);
    cudaGetSymbolAddress((void**)&gPh, g_Ph);
    cudaGetSymbolAddress((void**)&gPl, g_Pl);
    cudaGetSymbolAddress((void**)&gWc, g_Wc);
    cudaGetSymbolAddress((void**)&gbc, g_bc);

    cudaFuncSetAttribute(corr_hmma_kernel,
                         cudaFuncAttributeMaxDynamicSharedMemorySize, CORR_SMEM);

    const int ROWS = QN * TNT;  // 65536

    // 0) fold v_w2 @ W
    prep_w_kernel<<<DHD, DHD>>>(v_w2, v_b2, W);

    // 1) audio MLP: H = relu(audio @ a_w1 + a_b1); (Ah,Al) = split(H @ a_w2 + a_b2)
    gemm_nn_kernel<true,  false><<<dim3(ROWS / 128, DHD / 128), 256>>>(
        audio, a_w1, a_b1, gH, nullptr, nullptr, ROWS, DIN, DHD);
    gemm_nn_kernel<false, true ><<<dim3(ROWS / 128, DHD / 128), 256>>>(
        gH, a_w2, a_b2, nullptr, gAh, gAl, ROWS, DHD, DHD);

    // 2) video MLP + folded projection: (Ph,Pl) = split(relu(video@v_w1+v_b1) @ Wc + bc)
    gemm_nn_kernel<true,  false><<<dim3(ROWS / 128, DHD / 128), 256>>>(
        video, v_w1, v_b1, gH, nullptr, nullptr, ROWS, DIN, DHD);
    gemm_nn_kernel<false, true ><<<dim3(ROWS / 128, DHD / 128), 256>>>(
        gH, gWc, gbc, nullptr, gPh, gPl, ROWS, DHD, DHD);

    // 3) per-lag correlation on HMMA tensor cores (144 CTAs, one wave)
    corr_hmma_kernel<<<dim3(QN / 128, CN / 128, NLAG), 256, CORR_SMEM>>>(
        gAh, gAl, gPh, gPl);

    // 4) max over lags
    maxlag_kernel<<<(QN * CN) / 256, 256>>>(out);
}

// round 4
// speedup vs baseline: 2.6862x; 1.3049x over previous
#include <cuda_runtime.h>
#include <cuda_bf16.h>
#include <cstdint>

// Problem dims (fixed by the reference)
#define QN   512
#define CN   512
#define TNT  128
#define DIN  512
#define DHD  256
#define KCORR (TNT * DHD)   // 32768
#define MAXLAG 4
#define NLAG  9             // lags -4..4
#define MROWS (QN * TNT)    // 65536

// ---------------------------------------------------------------------------
// Scratch (static device globals; no allocation allowed)
// ---------------------------------------------------------------------------
__device__ __nv_bfloat16 g_Hh[MROWS * DHD];     // hidden hi (reused audio/video)
__device__ __nv_bfloat16 g_Hl[MROWS * DHD];     // hidden lo
__device__ __nv_bfloat16 g_Ah[MROWS * DHD];     // audio features hi  [Q, T*DH]
__device__ __nv_bfloat16 g_Al[MROWS * DHD];     // audio features lo
__device__ __nv_bfloat16 g_Ph[MROWS * DHD];     // projected video hi [C, T*DH]
__device__ __nv_bfloat16 g_Pl[MROWS * DHD];     // projected video lo
__device__ float g_Wc[DHD * DHD];               // folded v_w2 @ W (fp32)
__device__ float g_bc[DHD];                     // folded v_b2 @ W
// pre-split, pre-transposed weights: [N][K], K contiguous
__device__ __nv_bfloat16 g_W1ah[DHD * DIN], g_W1al[DHD * DIN];
__device__ __nv_bfloat16 g_W1vh[DHD * DIN], g_W1vl[DHD * DIN];
__device__ __nv_bfloat16 g_W2ah[DHD * DHD], g_W2al[DHD * DHD];
__device__ __nv_bfloat16 g_Wcth[DHD * DHD], g_Wctl[DHD * DHD];
__device__ float g_S [NLAG * QN * CN];          // per-lag scores

// ---------------------------------------------------------------------------
// Portable PTX helpers (valid on compute_103 virtual target)
// ---------------------------------------------------------------------------
__device__ __forceinline__ uint32_t smem_u32(const void* p) {
    uint32_t a;
    asm("{ .reg .u64 t; cvta.to.shared.u64 t, %1; cvt.u32.u64 %0, t; }"
        : "=r"(a) : "l"(p));
    return a;
}

#define CP_ASYNC_16(dst, src) \
    asm volatile("cp.async.ca.shared.global [%0], [%1], 16;" \
        :: "r"(dst), "l"(src) : "memory")
#define CP_ASYNC_COMMIT() asm volatile("cp.async.commit_group;" ::: "memory")
#define CP_ASYNC_WAIT_1() asm volatile("cp.async.wait_group 1;" ::: "memory")
#define CP_ASYNC_WAIT_0() asm volatile("cp.async.wait_group 0;" ::: "memory")

#define LDSM_X4(r, addr) \
    asm volatile("ldmatrix.sync.aligned.m8n8.x4.shared.b16 {%0,%1,%2,%3}, [%4];" \
        : "=r"((r)[0]), "=r"((r)[1]), "=r"((r)[2]), "=r"((r)[3]) : "r"(addr))

__device__ __forceinline__ void mma16816(float* c, const uint32_t* a,
                                         const uint32_t* b) {
    asm volatile(
        "mma.sync.aligned.m16n8k16.row.col.f32.bf16.bf16.f32 "
        "{%0,%1,%2,%3}, {%4,%5,%6,%7}, {%8,%9}, {%0,%1,%2,%3};"
        : "+f"(c[0]), "+f"(c[1]), "+f"(c[2]), "+f"(c[3])
        : "r"(a[0]), "r"(a[1]), "r"(a[2]), "r"(a[3]), "r"(b[0]), "r"(b[1]));
}

// ---------------------------------------------------------------------------
// Prep: fold v_w2 @ W -> g_Wc, g_bc
// ---------------------------------------------------------------------------
__global__ void prep_w_kernel(const float* __restrict__ v_w2,
                              const float* __restrict__ v_b2,
                              const float* __restrict__ W) {
    int i = blockIdx.x;
    int j = threadIdx.x;
    float acc = 0.f;
    #pragma unroll 8
    for (int k = 0; k < DHD; ++k)
        acc += v_w2[i * DHD + k] * W[k * DHD + j];
    g_Wc[i * DHD + j] = acc;
    if (i == 0) {
        float accb = 0.f;
        #pragma unroll 8
        for (int k = 0; k < DHD; ++k)
            accb += v_b2[k] * W[k * DHD + j];
        g_bc[j] = accb;
    }
}

// Prep: transpose + split fp32 [K, 256] -> bf16 hi/lo [256][K]
__global__ void split_t_kernel(const float* __restrict__ in,
                               __nv_bfloat16* __restrict__ oh,
                               __nv_bfloat16* __restrict__ ol, int K) {
    int n = blockIdx.x;
    for (int k = threadIdx.x; k < K; k += blockDim.x) {
        float v = in[(size_t)k * DHD + n];
        __nv_bfloat16 h = __float2bfloat16(v);
        __nv_bfloat16 l = __float2bfloat16(v - __bfloat162float(h));
        oh[(size_t)n * K + k] = h;
        ol[(size_t)n * K + k] = l;
    }
}

// ---------------------------------------------------------------------------
// Shared tiling constants (HMMA kernels)
// ---------------------------------------------------------------------------
#define BKC     32                  // K elems per chunk
#define ROWB    80                  // padded row stride bytes (64 data + 16)
#define TILE_PB (128 * ROWB)        // 10240
#define BUF_PB  (4 * TILE_PB)       // 4 tiles: Ah, Al, Bh, Bl
#define HMMA_SMEM (2 * BUF_PB)      // 81920

extern __shared__ char dsm[];

// ---------------------------------------------------------------------------
// MLP GEMM on HMMA:  O = split( (relu?)(A @ Bt' + bias) )
//   A: [M, K]  (fp32 if CONVERT_A, else bf16 hi/lo pair)
//   B: pre-split transposed weights [N][K] hi/lo (N=256 total, tile 128)
//   O: bf16 hi/lo [M, 256]
// 8 warps, warp tile 64x32; K chunks of 32; double buffered.
// ---------------------------------------------------------------------------
template <bool CONVERT_A, bool RELU>
__global__ __launch_bounds__(256, 1)
void mlp_hmma_kernel(const float* __restrict__ Af,
                     const __nv_bfloat16* __restrict__ Ahg,
                     const __nv_bfloat16* __restrict__ Alg,
                     const __nv_bfloat16* __restrict__ Bh,
                     const __nv_bfloat16* __restrict__ Bl,
                     const float* __restrict__ bias,
                     __nv_bfloat16* __restrict__ Oh,
                     __nv_bfloat16* __restrict__ Ol,
                     int K) {
    const uint32_t sb = smem_u32(dsm);
    const int tid  = threadIdx.x;
    const int wid  = tid >> 5;
    const int lane = tid & 31;
    const int bm = blockIdx.x * 128;
    const int bn = blockIdx.y * 128;
    const int NCH = K / BKC;

    const int wm = (wid >> 2) * 64;
    const int wn = (wid & 3) * 32;

    float acc[4][4][4];
    #pragma unroll
    for (int mi = 0; mi < 4; ++mi)
        #pragma unroll
        for (int nf = 0; nf < 4; ++nf)
            #pragma unroll
            for (int r = 0; r < 4; ++r) acc[mi][nf][r] = 0.f;

    // ldmatrix lane addressing
    const int aRow = wm + (lane & 15);
    const int aSeg = (lane >> 4) << 4;
    const int bg   = lane >> 3;
    const int bRow = wn + ((bg >> 1) << 3) + (lane & 7);
    const int bSeg = (bg & 1) << 4;

    // per-thread load mapping
    const int ldRow = tid >> 3;          // 0..31? no: tid/8 -> 0..31 for 256? tid>>3 = 0..31
    // (see unit-mapped loops below; kept simple)

    float4 areg[4];                      // CONVERT_A staging (16 floats)

    // ---- prefetch helpers ----
    auto prefetch_B = [&](int c, int buf) {
        const int k0 = c * BKC;
        const uint32_t base = sb + buf * BUF_PB;
        #pragma unroll
        for (int i = 0; i < 4; ++i) {
            int u = tid + i * 256;               // 0..1023
            int tile = 2 + (u >> 9);             // 2..3
            int w = u & 511;
            int row = w >> 2, seg = w & 3;
            uint32_t dst = base + tile * TILE_PB + row * ROWB + seg * 16;
            const __nv_bfloat16* src =
                ((u >> 9) == 0 ? Bh : Bl) + (size_t)(bn + row) * K + k0 + seg * 8;
            CP_ASYNC_16(dst, src);
        }
    };
    auto prefetch_A_bf16 = [&](int c, int buf) {
        const int k0 = c * BKC;
        const uint32_t base = sb + buf * BUF_PB;
        #pragma unroll
        for (int i = 0; i < 4; ++i) {
            int u = tid + i * 256;
            int tile = u >> 9;                   // 0..1
            int w = u & 511;
            int row = w >> 2, seg = w & 3;
            uint32_t dst = base + tile * TILE_PB + row * ROWB + seg * 16;
            const __nv_bfloat16* src =
                (tile == 0 ? Ahg : Alg) + (size_t)(bm + row) * K + k0 + seg * 8;
            CP_ASYNC_16(dst, src);
        }
    };
    auto ldg_A_f32 = [&](int c) {
        const int k0 = c * BKC;
        #pragma unroll
        for (int i = 0; i < 4; ++i) {
            int s = tid + i * 256;               // 0..1023
            int row = s >> 3, seg = s & 7;       // 4-float granules
            areg[i] = *(const float4*)&Af[(size_t)(bm + row) * K + k0 + seg * 4];
        }
    };
    auto sts_A_split = [&](int buf) {
        const uint32_t base = sb + buf * BUF_PB;
        #pragma unroll
        for (int i = 0; i < 4; ++i) {
            int s = tid + i * 256;
            int row = s >> 3, seg = s & 7;
            uint32_t off = row * ROWB + seg * 8;
            float4 v = areg[i];
            __nv_bfloat16 hx = __float2bfloat16(v.x);
            __nv_bfloat16 hy = __float2bfloat16(v.y);
            __nv_bfloat16 hz = __float2bfloat16(v.z);
            __nv_bfloat16 hw = __float2bfloat16(v.w);
            __nv_bfloat162 h01(hx, hy), h23(hz, hw);
            __nv_bfloat162 l01(__float2bfloat16(v.x - __bfloat162float(hx)),
                               __float2bfloat16(v.y - __bfloat162float(hy)));
            __nv_bfloat162 l23(__float2bfloat16(v.z - __bfloat162float(hz)),
                               __float2bfloat16(v.w - __bfloat162float(hw)));
            uint32_t hu0 = *(uint32_t*)&h01, hu1 = *(uint32_t*)&h23;
            uint32_t lu0 = *(uint32_t*)&l01, lu1 = *(uint32_t*)&l23;
            asm volatile("st.shared.v2.b32 [%0], {%1, %2};"
                         :: "r"(base + 0 * TILE_PB + off), "r"(hu0), "r"(hu1) : "memory");
            asm volatile("st.shared.v2.b32 [%0], {%1, %2};"
                         :: "r"(base + 1 * TILE_PB + off), "r"(lu0), "r"(lu1) : "memory");
        }
    };

    // ---- pipeline ----
    if (CONVERT_A) {
        ldg_A_f32(0);
        prefetch_B(0, 0);
        CP_ASYNC_COMMIT();
    } else {
        prefetch_A_bf16(0, 0);
        prefetch_B(0, 0);
        CP_ASYNC_COMMIT();
    }

    for (int c = 0; c < NCH; ++c) {
        const int buf = c & 1;
        if (CONVERT_A) {
            sts_A_split(buf);
            if (c + 1 < NCH) {
                prefetch_B(c + 1, buf ^ 1);
                CP_ASYNC_COMMIT();
                CP_ASYNC_WAIT_1();
            } else {
                CP_ASYNC_WAIT_0();
            }
            __syncthreads();
            if (c + 1 < NCH) ldg_A_f32(c + 1);
        } else {
            if (c + 1 < NCH) {
                prefetch_A_bf16(c + 1, buf ^ 1);
                prefetch_B(c + 1, buf ^ 1);
                CP_ASYNC_COMMIT();
                CP_ASYNC_WAIT_1();
            } else {
                CP_ASYNC_WAIT_0();
            }
            __syncthreads();
        }

        const uint32_t tb  = sb + buf * BUF_PB;
        const uint32_t ahB = tb + 0 * TILE_PB;
        const uint32_t alB = tb + 1 * TILE_PB;
        const uint32_t bhB = tb + 2 * TILE_PB;
        const uint32_t blB = tb + 3 * TILE_PB;

        #pragma unroll
        for (int ks = 0; ks < 2; ++ks) {
            const int kbyte = ks * 32;
            uint32_t ah[4][4], al[4][4], ph[4][2], pl[4][2];
            #pragma unroll
            for (int mi = 0; mi < 4; ++mi) {
                uint32_t off = (uint32_t)(aRow + mi * 16) * ROWB + kbyte + aSeg;
                LDSM_X4(ah[mi], ahB + off);
                LDSM_X4(al[mi], alB + off);
            }
            #pragma unroll
            for (int ni = 0; ni < 2; ++ni) {
                uint32_t off = (uint32_t)(bRow + ni * 16) * ROWB + kbyte + bSeg;
                uint32_t r[4];
                LDSM_X4(r, bhB + off);
                ph[2 * ni][0] = r[0]; ph[2 * ni][1] = r[1];
                ph[2 * ni + 1][0] = r[2]; ph[2 * ni + 1][1] = r[3];
                LDSM_X4(r, blB + off);
                pl[2 * ni][0] = r[0]; pl[2 * ni][1] = r[1];
                pl[2 * ni + 1][0] = r[2]; pl[2 * ni + 1][1] = r[3];
            }
            #pragma unroll
            for (int mi = 0; mi < 4; ++mi)
                #pragma unroll
                for (int nf = 0; nf < 4; ++nf) {
                    mma16816(acc[mi][nf], ah[mi], ph[nf]);  // hi*hi
                    mma16816(acc[mi][nf], ah[mi], pl[nf]);  // hi*lo
                    mma16816(acc[mi][nf], al[mi], ph[nf]);  // lo*hi
                }
        }
        __syncthreads();
    }

    // Epilogue: bias (+relu) -> split hi/lo -> STG bf16x2
    #pragma unroll
    for (int mi = 0; mi < 4; ++mi) {
        int r0 = bm + wm + mi * 16 + (lane >> 2);
        #pragma unroll
        for (int nf = 0; nf < 4; ++nf) {
            int cn = bn + wn + nf * 8 + 2 * (lane & 3);
            float b0 = bias[cn], b1 = bias[cn + 1];
            #pragma unroll
            for (int half = 0; half < 2; ++half) {
                int r = r0 + half * 8;
                float o0 = acc[mi][nf][2 * half + 0] + b0;
                float o1 = acc[mi][nf][2 * half + 1] + b1;
                if (RELU) { o0 = fmaxf(o0, 0.f); o1 = fmaxf(o1, 0.f); }
                __nv_bfloat16 h0 = __float2bfloat16(o0);
                __nv_bfloat16 h1 = __float2bfloat16(o1);
                __nv_bfloat162 hh(h0, h1);
                __nv_bfloat162 ll(__float2bfloat16(o0 - __bfloat162float(h0)),
                                  __float2bfloat16(o1 - __bfloat162float(h1)));
                *(__nv_bfloat162*)&Oh[(size_t)r * DHD + cn] = hh;
                *(__nv_bfloat162*)&Ol[(size_t)r * DHD + cn] = ll;
            }
        }
    }
}

// ---------------------------------------------------------------------------
// Correlation on HMMA (split hi/lo), as R3 (proven): 128x128 tile per
// (q-tile, c-tile, lag); 8 warps 64x32; K chunks 32; cp.async double buffer.
// ---------------------------------------------------------------------------
#define NCHUNK  (KCORR / BKC)       // 1024

__device__ __forceinline__ void corr_prefetch(
    uint32_t sb, int buf, int c, int bm, int bn, int lag,
    const __nv_bfloat16* __restrict__ Ah, const __nv_bfloat16* __restrict__ Al,
    const __nv_bfloat16* __restrict__ Ph, const __nv_bfloat16* __restrict__ Pl,
    int tid)
{
    const int k0 = c * BKC;
    const int t  = c >> 3;
    const int d0 = (c & 7) << 5;
    const int ts = (t + lag + TNT) & (TNT - 1);
    const int kb = ts * DHD + d0;

    const uint32_t base = sb + buf * BUF_PB;
    #pragma unroll
    for (int i = 0; i < 8; ++i) {
        int u    = tid + i * 256;
        int tile = u >> 9;
        int w    = u & 511;
        int row  = w >> 2;
        int seg  = w & 3;
        uint32_t dst = base + tile * TILE_PB + row * ROWB + seg * 16;
        const __nv_bfloat16* src;
        if (tile == 0)      src = Ah + (size_t)(bm + row) * KCORR + k0 + seg * 8;
        else if (tile == 1) src = Al + (size_t)(bm + row) * KCORR + k0 + seg * 8;
        else if (tile == 2) src = Ph + (size_t)(bn + row) * KCORR + kb + seg * 8;
        else                src = Pl + (size_t)(bn + row) * KCORR + kb + seg * 8;
        CP_ASYNC_16(dst, src);
    }
    CP_ASYNC_COMMIT();
}

__global__ __launch_bounds__(256, 1)
void corr_hmma_kernel(const __nv_bfloat16* __restrict__ Ah,
                      const __nv_bfloat16* __restrict__ Al,
                      const __nv_bfloat16* __restrict__ Ph,
                      const __nv_bfloat16* __restrict__ Pl) {
    const uint32_t sb = smem_u32(dsm);
    const int tid  = threadIdx.x;
    const int wid  = tid >> 5;
    const int lane = tid & 31;
    const int bm = blockIdx.x * 128;
    const int bn = blockIdx.y * 128;
    const int lag = (int)blockIdx.z - MAXLAG;

    const int wm = (wid >> 2) * 64;
    const int wn = (wid & 3) * 32;

    float acc[4][4][4];
    #pragma unroll
    for (int mi = 0; mi < 4; ++mi)
        #pragma unroll
        for (int nf = 0; nf < 4; ++nf)
            #pragma unroll
            for (int r = 0; r < 4; ++r) acc[mi][nf][r] = 0.f;

    const int aRow = wm + (lane & 15);
    const int aSeg = (lane >> 4) << 4;
    const int bg   = lane >> 3;
    const int bRow = wn + ((bg >> 1) << 3) + (lane & 7);
    const int bSeg = (bg & 1) << 4;

    corr_prefetch(sb, 0, 0, bm, bn, lag, Ah, Al, Ph, Pl, tid);

    for (int c = 0; c < NCHUNK; ++c) {
        const int buf = c & 1;
        if (c + 1 < NCHUNK) {
            corr_prefetch(sb, buf ^ 1, c + 1, bm, bn, lag, Ah, Al, Ph, Pl, tid);
            CP_ASYNC_WAIT_1();
        } else {
            CP_ASYNC_WAIT_0();
        }
        __syncthreads();

        const uint32_t tb  = sb + buf * BUF_PB;
        const uint32_t ahB = tb + 0 * TILE_PB;
        const uint32_t alB = tb + 1 * TILE_PB;
        const uint32_t phB = tb + 2 * TILE_PB;
        const uint32_t plB = tb + 3 * TILE_PB;

        #pragma unroll
        for (int ks = 0; ks < 2; ++ks) {
            const int kbyte = ks * 32;
            uint32_t ah[4][4], al[4][4], ph[4][2], pl[4][2];
            #pragma unroll
            for (int mi = 0; mi < 4; ++mi) {
                uint32_t off = (uint32_t)(aRow + mi * 16) * ROWB + kbyte + aSeg;
                LDSM_X4(ah[mi], ahB + off);
                LDSM_X4(al[mi], alB + off);
            }
            #pragma unroll
            for (int ni = 0; ni < 2; ++ni) {
                uint32_t off = (uint32_t)(bRow + ni * 16) * ROWB + kbyte + bSeg;
                uint32_t r[4];
                LDSM_X4(r, phB + off);
                ph[2 * ni][0] = r[0]; ph[2 * ni][1] = r[1];
                ph[2 * ni + 1][0] = r[2]; ph[2 * ni + 1][1] = r[3];
                LDSM_X4(r, plB + off);
                pl[2 * ni][0] = r[0]; pl[2 * ni][1] = r[1];
                pl[2 * ni + 1][0] = r[2]; pl[2 * ni + 1][1] = r[3];
            }
            #pragma unroll
            for (int mi = 0; mi < 4; ++mi)
                #pragma unroll
                for (int nf = 0; nf < 4; ++nf) {
                    mma16816(acc[mi][nf], ah[mi], ph[nf]);
                    mma16816(acc[mi][nf], ah[mi], pl[nf]);
                    mma16816(acc[mi][nf], al[mi], ph[nf]);
                }
        }
        __syncthreads();
    }

    float* Sz = g_S + (size_t)blockIdx.z * QN * CN;
    #pragma unroll
    for (int mi = 0; mi < 4; ++mi) {
        int r0 = bm + wm + mi * 16 + (lane >> 2);
        #pragma unroll
        for (int nf = 0; nf < 4; ++nf) {
            int col = bn + wn + nf * 8 + 2 * (lane & 3);
            float2 v0 = {acc[mi][nf][0], acc[mi][nf][1]};
            float2 v1 = {acc[mi][nf][2], acc[mi][nf][3]};
            *(float2*)&Sz[(size_t)r0 * CN + col]       = v0;
            *(float2*)&Sz[(size_t)(r0 + 8) * CN + col] = v1;
        }
    }
}

// ---------------------------------------------------------------------------
// Final max over lags
// ---------------------------------------------------------------------------
__global__ void maxlag_kernel(float* __restrict__ out) {
    int idx = blockIdx.x * blockDim.x + threadIdx.x;
    float m = g_S[idx];
    #pragma unroll
    for (int j = 1; j < NLAG; ++j)
        m = fmaxf(m, g_S[(size_t)j * QN * CN + idx]);
    out[idx] = m;
}

// ---------------------------------------------------------------------------
// Launch
// ---------------------------------------------------------------------------
extern "C" void kernel_launch(void* const* d_in, const int* in_sizes, int n_in,
                              void* d_out, int out_size) {
    const float* audio = (const float*)d_in[0];
    const float* video = (const float*)d_in[1];
    const float* a_w1  = (const float*)d_in[2];
    const float* a_b1  = (const float*)d_in[3];
    const float* a_w2  = (const float*)d_in[4];
    const float* a_b2  = (const float*)d_in[5];
    const float* v_w1  = (const float*)d_in[6];
    const float* v_b1  = (const float*)d_in[7];
    const float* v_w2  = (const float*)d_in[8];
    const float* v_b2  = (const float*)d_in[9];
    const float* W     = (const float*)d_in[10];
    float* out = (float*)d_out;

    float *gWc, *gbc;
    __nv_bfloat16 *gHh, *gHl, *gAh, *gAl, *gPh, *gPl;
    __nv_bfloat16 *gW1ah, *gW1al, *gW1vh, *gW1vl, *gW2ah, *gW2al, *gWcth, *gWctl;
    cudaGetSymbolAddress((void**)&gHh, g_Hh);
    cudaGetSymbolAddress((void**)&gHl, g_Hl);
    cudaGetSymbolAddress((void**)&gAh, g_Ah);
    cudaGetSymbolAddress((void**)&gAl, g_Al);
    cudaGetSymbolAddress((void**)&gPh, g_Ph);
    cudaGetSymbolAddress((void**)&gPl, g_Pl);
    cudaGetSymbolAddress((void**)&gWc, g_Wc);
    cudaGetSymbolAddress((void**)&gbc, g_bc);
    cudaGetSymbolAddress((void**)&gW1ah, g_W1ah);
    cudaGetSymbolAddress((void**)&gW1al, g_W1al);
    cudaGetSymbolAddress((void**)&gW1vh, g_W1vh);
    cudaGetSymbolAddress((void**)&gW1vl, g_W1vl);
    cudaGetSymbolAddress((void**)&gW2ah, g_W2ah);
    cudaGetSymbolAddress((void**)&gW2al, g_W2al);
    cudaGetSymbolAddress((void**)&gWcth, g_Wcth);
    cudaGetSymbolAddress((void**)&gWctl, g_Wctl);

    cudaFuncSetAttribute(corr_hmma_kernel,
                         cudaFuncAttributeMaxDynamicSharedMemorySize, HMMA_SMEM);
    cudaFuncSetAttribute(mlp_hmma_kernel<true, true>,
                         cudaFuncAttributeMaxDynamicSharedMemorySize, HMMA_SMEM);
    cudaFuncSetAttribute(mlp_hmma_kernel<false, false>,
                         cudaFuncAttributeMaxDynamicSharedMemorySize, HMMA_SMEM);

    // 0) prep: fold Wc, split+transpose all weights
    prep_w_kernel<<<DHD, DHD>>>(v_w2, v_b2, W);
    split_t_kernel<<<DHD, 256>>>(a_w1, gW1ah, gW1al, DIN);
    split_t_kernel<<<DHD, 256>>>(v_w1, gW1vh, gW1vl, DIN);
    split_t_kernel<<<DHD, 256>>>(a_w2, gW2ah, gW2al, DHD);
    split_t_kernel<<<DHD, 256>>>(gWc,  gWcth, gWctl, DHD);

    const dim3 mlp_grid(MROWS / 128, DHD / 128);   // 512 x 2

    // 1) audio MLP on HMMA
    mlp_hmma_kernel<true,  true ><<<mlp_grid, 256, HMMA_SMEM>>>(
        audio, nullptr, nullptr, gW1ah, gW1al, a_b1, gHh, gHl, DIN);
    mlp_hmma_kernel<false, false><<<mlp_grid, 256, HMMA_SMEM>>>(
        nullptr, gHh, gHl, gW2ah, gW2al, a_b2, gAh, gAl, DHD);

    // 2) video MLP + folded projection on HMMA
    mlp_hmma_kernel<true,  true ><<<mlp_grid, 256, HMMA_SMEM>>>(
        video, nullptr, nullptr, gW1vh, gW1vl, v_b1, gHh, gHl, DIN);
    mlp_hmma_kernel<false, false><<<mlp_grid, 256, HMMA_SMEM>>>(
        nullptr, gHh, gHl, gWcth, gWctl, gbc, gPh, gPl, DHD);

    // 3) per-lag correlation on HMMA (144 CTAs, one wave)
    corr_hmma_kernel<<<dim3(QN / 128, CN / 128, NLAG), 256, HMMA_SMEM>>>(
        gAh, gAl, gPh, gPl);

    // 4) max over lags
    maxlag_kernel<<<(QN * CN) / 256, 256>>>(out);
}

// round 5
// speedup vs baseline: 2.8906x; 1.0761x over previous
#include <cuda_runtime.h>
#include <cuda_bf16.h>
#include <cstdint>

// Problem dims (fixed by the reference)
#define QN   512
#define CN   512
#define TNT  128
#define DIN  512
#define DHD  256
#define KCORR (TNT * DHD)   // 32768
#define MAXLAG 4
#define NLAG  9             // lags -4..4
#define MROWS (QN * TNT)    // 65536

// ---------------------------------------------------------------------------
// Scratch (static device globals; no allocation allowed)
// ---------------------------------------------------------------------------
__device__ __nv_bfloat16 g_Hh[MROWS * DHD];     // hidden hi (reused audio/video)
__device__ __nv_bfloat16 g_Hl[MROWS * DHD];     // hidden lo
__device__ __nv_bfloat16 g_Ah[MROWS * DHD];     // audio features hi  [Q, T*DH]
__device__ __nv_bfloat16 g_Al[MROWS * DHD];     // audio features lo
__device__ __nv_bfloat16 g_Ph[MROWS * DHD];     // projected video hi [C, T*DH]
__device__ __nv_bfloat16 g_Pl[MROWS * DHD];     // projected video lo
__device__ float g_Wc[DHD * DHD];               // folded v_w2 @ W (fp32)
__device__ float g_bc[DHD];                     // folded v_b2 @ W
// pre-split, pre-transposed weights: [N][K], K contiguous
__device__ __nv_bfloat16 g_W1ah[DHD * DIN], g_W1al[DHD * DIN];
__device__ __nv_bfloat16 g_W1vh[DHD * DIN], g_W1vl[DHD * DIN];
__device__ __nv_bfloat16 g_W2ah[DHD * DHD], g_W2al[DHD * DHD];
__device__ __nv_bfloat16 g_Wcth[DHD * DHD], g_Wctl[DHD * DHD];
__device__ float g_S [NLAG * QN * CN];          // per-lag scores

// ---------------------------------------------------------------------------
// Portable PTX helpers (valid on compute_103 virtual target)
// ---------------------------------------------------------------------------
__device__ __forceinline__ uint32_t smem_u32(const void* p) {
    uint32_t a;
    asm("{ .reg .u64 t; cvta.to.shared.u64 t, %1; cvt.u32.u64 %0, t; }"
        : "=r"(a) : "l"(p));
    return a;
}

#define CP_ASYNC_16(dst, src) \
    asm volatile("cp.async.ca.shared.global [%0], [%1], 16;" \
        :: "r"(dst), "l"(src) : "memory")
#define CP_ASYNC_CG_16(dst, src) \
    asm volatile("cp.async.cg.shared.global [%0], [%1], 16;" \
        :: "r"(dst), "l"(src) : "memory")
#define CP_ASYNC_COMMIT() asm volatile("cp.async.commit_group;" ::: "memory")
#define CP_ASYNC_WAIT_1() asm volatile("cp.async.wait_group 1;" ::: "memory")
#define CP_ASYNC_WAIT_0() asm volatile("cp.async.wait_group 0;" ::: "memory")

#define LDSM_X4(r, addr) \
    asm volatile("ldmatrix.sync.aligned.m8n8.x4.shared.b16 {%0,%1,%2,%3}, [%4];" \
        : "=r"((r)[0]), "=r"((r)[1]), "=r"((r)[2]), "=r"((r)[3]) : "r"(addr))

__device__ __forceinline__ void mma16816(float* c, const uint32_t* a,
                                         const uint32_t* b) {
    asm volatile(
        "mma.sync.aligned.m16n8k16.row.col.f32.bf16.bf16.f32 "
        "{%0,%1,%2,%3}, {%4,%5,%6,%7}, {%8,%9}, {%0,%1,%2,%3};"
        : "+f"(c[0]), "+f"(c[1]), "+f"(c[2]), "+f"(c[3])
        : "r"(a[0]), "r"(a[1]), "r"(a[2]), "r"(a[3]), "r"(b[0]), "r"(b[1]));
}

// ---------------------------------------------------------------------------
// Prep: fold v_w2 @ W -> g_Wc, g_bc
// ---------------------------------------------------------------------------
__global__ void prep_w_kernel(const float* __restrict__ v_w2,
                              const float* __restrict__ v_b2,
                              const float* __restrict__ W) {
    int i = blockIdx.x;
    int j = threadIdx.x;
    float acc = 0.f;
    #pragma unroll 8
    for (int k = 0; k < DHD; ++k)
        acc += v_w2[i * DHD + k] * W[k * DHD + j];
    g_Wc[i * DHD + j] = acc;
    if (i == 0) {
        float accb = 0.f;
        #pragma unroll 8
        for (int k = 0; k < DHD; ++k)
            accb += v_b2[k] * W[k * DHD + j];
        g_bc[j] = accb;
    }
}

// Prep: transpose + split fp32 [K, 256] -> bf16 hi/lo [256][K]
__global__ void split_t_kernel(const float* __restrict__ in,
                               __nv_bfloat16* __restrict__ oh,
                               __nv_bfloat16* __restrict__ ol, int K) {
    int n = blockIdx.x;
    for (int k = threadIdx.x; k < K; k += blockDim.x) {
        float v = in[(size_t)k * DHD + n];
        __nv_bfloat16 h = __float2bfloat16(v);
        __nv_bfloat16 l = __float2bfloat16(v - __bfloat162float(h));
        oh[(size_t)n * K + k] = h;
        ol[(size_t)n * K + k] = l;
    }
}

// ---------------------------------------------------------------------------
// MLP tiling constants (unchanged from R4)
// ---------------------------------------------------------------------------
#define BKC     32                  // K elems per chunk (MLP)
#define ROWB    80                  // padded row stride bytes (64 data + 16)
#define TILE_PB (128 * ROWB)        // 10240
#define BUF_PB  (4 * TILE_PB)       // 4 tiles: Ah, Al, Bh, Bl
#define HMMA_SMEM (2 * BUF_PB)      // 81920

extern __shared__ char dsm[];

// ---------------------------------------------------------------------------
// MLP GEMM on HMMA (unchanged from R4, proven)
// ---------------------------------------------------------------------------
template <bool CONVERT_A, bool RELU>
__global__ __launch_bounds__(256, 1)
void mlp_hmma_kernel(const float* __restrict__ Af,
                     const __nv_bfloat16* __restrict__ Ahg,
                     const __nv_bfloat16* __restrict__ Alg,
                     const __nv_bfloat16* __restrict__ Bh,
                     const __nv_bfloat16* __restrict__ Bl,
                     const float* __restrict__ bias,
                     __nv_bfloat16* __restrict__ Oh,
                     __nv_bfloat16* __restrict__ Ol,
                     int K) {
    const uint32_t sb = smem_u32(dsm);
    const int tid  = threadIdx.x;
    const int wid  = tid >> 5;
    const int lane = tid & 31;
    const int bm = blockIdx.x * 128;
    const int bn = blockIdx.y * 128;
    const int NCH = K / BKC;

    const int wm = (wid >> 2) * 64;
    const int wn = (wid & 3) * 32;

    float acc[4][4][4];
    #pragma unroll
    for (int mi = 0; mi < 4; ++mi)
        #pragma unroll
        for (int nf = 0; nf < 4; ++nf)
            #pragma unroll
            for (int r = 0; r < 4; ++r) acc[mi][nf][r] = 0.f;

    const int aRow = wm + (lane & 15);
    const int aSeg = (lane >> 4) << 4;
    const int bg   = lane >> 3;
    const int bRow = wn + ((bg >> 1) << 3) + (lane & 7);
    const int bSeg = (bg & 1) << 4;

    float4 areg[4];

    auto prefetch_B = [&](int c, int buf) {
        const int k0 = c * BKC;
        const uint32_t base = sb + buf * BUF_PB;
        #pragma unroll
        for (int i = 0; i < 4; ++i) {
            int u = tid + i * 256;
            int tile = 2 + (u >> 9);
            int w = u & 511;
            int row = w >> 2, seg = w & 3;
            uint32_t dst = base + tile * TILE_PB + row * ROWB + seg * 16;
            const __nv_bfloat16* src =
                ((u >> 9) == 0 ? Bh : Bl) + (size_t)(bn + row) * K + k0 + seg * 8;
            CP_ASYNC_16(dst, src);
        }
    };
    auto prefetch_A_bf16 = [&](int c, int buf) {
        const int k0 = c * BKC;
        const uint32_t base = sb + buf * BUF_PB;
        #pragma unroll
        for (int i = 0; i < 4; ++i) {
            int u = tid + i * 256;
            int tile = u >> 9;
            int w = u & 511;
            int row = w >> 2, seg = w & 3;
            uint32_t dst = base + tile * TILE_PB + row * ROWB + seg * 16;
            const __nv_bfloat16* src =
                (tile == 0 ? Ahg : Alg) + (size_t)(bm + row) * K + k0 + seg * 8;
            CP_ASYNC_16(dst, src);
        }
    };
    auto ldg_A_f32 = [&](int c) {
        const int k0 = c * BKC;
        #pragma unroll
        for (int i = 0; i < 4; ++i) {
            int s = tid + i * 256;
            int row = s >> 3, seg = s & 7;
            areg[i] = *(const float4*)&Af[(size_t)(bm + row) * K + k0 + seg * 4];
        }
    };
    auto sts_A_split = [&](int buf) {
        const uint32_t base = sb + buf * BUF_PB;
        #pragma unroll
        for (int i = 0; i < 4; ++i) {
            int s = tid + i * 256;
            int row = s >> 3, seg = s & 7;
            uint32_t off = row * ROWB + seg * 8;
            float4 v = areg[i];
            __nv_bfloat16 hx = __float2bfloat16(v.x);
            __nv_bfloat16 hy = __float2bfloat16(v.y);
            __nv_bfloat16 hz = __float2bfloat16(v.z);
            __nv_bfloat16 hw = __float2bfloat16(v.w);
            __nv_bfloat162 h01(hx, hy), h23(hz, hw);
            __nv_bfloat162 l01(__float2bfloat16(v.x - __bfloat162float(hx)),
                               __float2bfloat16(v.y - __bfloat162float(hy)));
            __nv_bfloat162 l23(__float2bfloat16(v.z - __bfloat162float(hz)),
                               __float2bfloat16(v.w - __bfloat162float(hw)));
            uint32_t hu0 = *(uint32_t*)&h01, hu1 = *(uint32_t*)&h23;
            uint32_t lu0 = *(uint32_t*)&l01, lu1 = *(uint32_t*)&l23;
            asm volatile("st.shared.v2.b32 [%0], {%1, %2};"
                         :: "r"(base + 0 * TILE_PB + off), "r"(hu0), "r"(hu1) : "memory");
            asm volatile("st.shared.v2.b32 [%0], {%1, %2};"
                         :: "r"(base + 1 * TILE_PB + off), "r"(lu0), "r"(lu1) : "memory");
        }
    };

    if (CONVERT_A) {
        ldg_A_f32(0);
        prefetch_B(0, 0);
        CP_ASYNC_COMMIT();
    } else {
        prefetch_A_bf16(0, 0);
        prefetch_B(0, 0);
        CP_ASYNC_COMMIT();
    }

    for (int c = 0; c < NCH; ++c) {
        const int buf = c & 1;
        if (CONVERT_A) {
            sts_A_split(buf);
            if (c + 1 < NCH) {
                prefetch_B(c + 1, buf ^ 1);
                CP_ASYNC_COMMIT();
                CP_ASYNC_WAIT_1();
            } else {
                CP_ASYNC_WAIT_0();
            }
            __syncthreads();
            if (c + 1 < NCH) ldg_A_f32(c + 1);
        } else {
            if (c + 1 < NCH) {
                prefetch_A_bf16(c + 1, buf ^ 1);
                prefetch_B(c + 1, buf ^ 1);
                CP_ASYNC_COMMIT();
                CP_ASYNC_WAIT_1();
            } else {
                CP_ASYNC_WAIT_0();
            }
            __syncthreads();
        }

        const uint32_t tb  = sb + buf * BUF_PB;
        const uint32_t ahB = tb + 0 * TILE_PB;
        const uint32_t alB = tb + 1 * TILE_PB;
        const uint32_t bhB = tb + 2 * TILE_PB;
        const uint32_t blB = tb + 3 * TILE_PB;

        #pragma unroll
        for (int ks = 0; ks < 2; ++ks) {
            const int kbyte = ks * 32;
            uint32_t ah[4][4], al[4][4], ph[4][2], pl[4][2];
            #pragma unroll
            for (int mi = 0; mi < 4; ++mi) {
                uint32_t off = (uint32_t)(aRow + mi * 16) * ROWB + kbyte + aSeg;
                LDSM_X4(ah[mi], ahB + off);
                LDSM_X4(al[mi], alB + off);
            }
            #pragma unroll
            for (int ni = 0; ni < 2; ++ni) {
                uint32_t off = (uint32_t)(bRow + ni * 16) * ROWB + kbyte + bSeg;
                uint32_t r[4];
                LDSM_X4(r, bhB + off);
                ph[2 * ni][0] = r[0]; ph[2 * ni][1] = r[1];
                ph[2 * ni + 1][0] = r[2]; ph[2 * ni + 1][1] = r[3];
                LDSM_X4(r, blB + off);
                pl[2 * ni][0] = r[0]; pl[2 * ni][1] = r[1];
                pl[2 * ni + 1][0] = r[2]; pl[2 * ni + 1][1] = r[3];
            }
            #pragma unroll
            for (int mi = 0; mi < 4; ++mi)
                #pragma unroll
                for (int nf = 0; nf < 4; ++nf) {
                    mma16816(acc[mi][nf], ah[mi], ph[nf]);
                    mma16816(acc[mi][nf], ah[mi], pl[nf]);
                    mma16816(acc[mi][nf], al[mi], ph[nf]);
                }
        }
        __syncthreads();
    }

    #pragma unroll
    for (int mi = 0; mi < 4; ++mi) {
        int r0 = bm + wm + mi * 16 + (lane >> 2);
        #pragma unroll
        for (int nf = 0; nf < 4; ++nf) {
            int cn = bn + wn + nf * 8 + 2 * (lane & 3);
            float b0 = bias[cn], b1 = bias[cn + 1];
            #pragma unroll
            for (int half = 0; half < 2; ++half) {
                int r = r0 + half * 8;
                float o0 = acc[mi][nf][2 * half + 0] + b0;
                float o1 = acc[mi][nf][2 * half + 1] + b1;
                if (RELU) { o0 = fmaxf(o0, 0.f); o1 = fmaxf(o1, 0.f); }
                __nv_bfloat16 h0 = __float2bfloat16(o0);
                __nv_bfloat16 h1 = __float2bfloat16(o1);
                __nv_bfloat162 hh(h0, h1);
                __nv_bfloat162 ll(__float2bfloat16(o0 - __bfloat162float(h0)),
                                  __float2bfloat16(o1 - __bfloat162float(h1)));
                *(__nv_bfloat162*)&Oh[(size_t)r * DHD + cn] = hh;
                *(__nv_bfloat162*)&Ol[(size_t)r * DHD + cn] = ll;
            }
        }
    }
}

// ---------------------------------------------------------------------------
// Correlation on HMMA, v2: BKC=64 chunks, explicit ks software pipeline.
//   one CTA per (q-tile 128, c-tile 128, lag); 8 warps, warp tile 64x32.
// ---------------------------------------------------------------------------
#define BKC2     64
#define NCHUNK2  (KCORR / BKC2)      // 512
#define ROWB2    144                 // 128 data + 16 pad
#define TILE2_PB (128 * ROWB2)       // 18432
#define BUF2_PB  (4 * TILE2_PB)      // 73728
#define CORR_SMEM (2 * BUF2_PB)      // 147456

__device__ __forceinline__ void corr_prefetch2(
    uint32_t sb, int buf, int c, int bm, int bn, int lag,
    const __nv_bfloat16* __restrict__ Ah, const __nv_bfloat16* __restrict__ Al,
    const __nv_bfloat16* __restrict__ Ph, const __nv_bfloat16* __restrict__ Pl,
    int tid)
{
    const int k0 = c * BKC2;
    const int t  = c >> 2;                       // k0 / 256
    const int d0 = (c & 3) << 6;                 // k0 % 256
    const int ts = (t + lag + TNT) & (TNT - 1);
    const int kb = ts * DHD + d0;

    const uint32_t base = sb + buf * BUF2_PB;
    #pragma unroll
    for (int i = 0; i < 16; ++i) {
        int u    = tid + i * 256;                // 0..4095
        int tile = u >> 10;                      // 0..3
        int w    = u & 1023;
        int row  = w >> 3;                       // 0..127
        int seg  = w & 7;                        // 16B segment
        uint32_t dst = base + tile * TILE2_PB + row * ROWB2 + seg * 16;
        const __nv_bfloat16* src;
        if (tile == 0)      src = Ah + (size_t)(bm + row) * KCORR + k0 + seg * 8;
        else if (tile == 1) src = Al + (size_t)(bm + row) * KCORR + k0 + seg * 8;
        else if (tile == 2) src = Ph + (size_t)(bn + row) * KCORR + kb + seg * 8;
        else                src = Pl + (size_t)(bn + row) * KCORR + kb + seg * 8;
        CP_ASYNC_CG_16(dst, src);
    }
    CP_ASYNC_COMMIT();
}

__global__ __launch_bounds__(256, 1)
void corr_hmma_kernel(const __nv_bfloat16* __restrict__ Ah,
                      const __nv_bfloat16* __restrict__ Al,
                      const __nv_bfloat16* __restrict__ Ph,
                      const __nv_bfloat16* __restrict__ Pl) {
    const uint32_t sb = smem_u32(dsm);
    const int tid  = threadIdx.x;
    const int wid  = tid >> 5;
    const int lane = tid & 31;
    const int bm = blockIdx.x * 128;
    const int bn = blockIdx.y * 128;
    const int lag = (int)blockIdx.z - MAXLAG;

    const int wm = (wid >> 2) * 64;
    const int wn = (wid & 3) * 32;

    float acc[4][4][4];
    #pragma unroll
    for (int mi = 0; mi < 4; ++mi)
        #pragma unroll
        for (int nf = 0; nf < 4; ++nf)
            #pragma unroll
            for (int r = 0; r < 4; ++r) acc[mi][nf][r] = 0.f;

    const int aRow = wm + (lane & 15);
    const int aSeg = (lane >> 4) << 4;
    const int bg   = lane >> 3;
    const int bRow = wn + ((bg >> 1) << 3) + (lane & 7);
    const int bSeg = (bg & 1) << 4;

    // double-buffered fragment registers (ks pipeline)
    uint32_t fah[2][4][4], fal[2][4][4], fbh[2][4][2], fbl[2][4][2];

    corr_prefetch2(sb, 0, 0, bm, bn, lag, Ah, Al, Ph, Pl, tid);

    for (int c = 0; c < NCHUNK2; ++c) {
        const int buf = c & 1;
        if (c + 1 < NCHUNK2) {
            corr_prefetch2(sb, buf ^ 1, c + 1, bm, bn, lag, Ah, Al, Ph, Pl, tid);
            CP_ASYNC_WAIT_1();
        } else {
            CP_ASYNC_WAIT_0();
        }
        __syncthreads();

        const uint32_t tb  = sb + buf * BUF2_PB;
        const uint32_t ahB = tb + 0 * TILE2_PB;
        const uint32_t alB = tb + 1 * TILE2_PB;
        const uint32_t phB = tb + 2 * TILE2_PB;
        const uint32_t plB = tb + 3 * TILE2_PB;

        // load fragments for ks = 0
        {
            #pragma unroll
            for (int mi = 0; mi < 4; ++mi) {
                uint32_t off = (uint32_t)(aRow + mi * 16) * ROWB2 + aSeg;
                LDSM_X4(fah[0][mi], ahB + off);
                LDSM_X4(fal[0][mi], alB + off);
            }
            #pragma unroll
            for (int ni = 0; ni < 2; ++ni) {
                uint32_t off = (uint32_t)(bRow + ni * 16) * ROWB2 + bSeg;
                uint32_t r[4];
                LDSM_X4(r, phB + off);
                fbh[0][2 * ni][0] = r[0]; fbh[0][2 * ni][1] = r[1];
                fbh[0][2 * ni + 1][0] = r[2]; fbh[0][2 * ni + 1][1] = r[3];
                LDSM_X4(r, plB + off);
                fbl[0][2 * ni][0] = r[0]; fbl[0][2 * ni][1] = r[1];
                fbl[0][2 * ni + 1][0] = r[2]; fbl[0][2 * ni + 1][1] = r[3];
            }
        }

        #pragma unroll
        for (int ks = 0; ks < 4; ++ks) {
            const int cur = ks & 1;
            if (ks < 3) {
                const int nxt = cur ^ 1;
                const int kbyte = (ks + 1) * 32;
                #pragma unroll
                for (int mi = 0; mi < 4; ++mi) {
                    uint32_t off = (uint32_t)(aRow + mi * 16) * ROWB2 + kbyte + aSeg;
                    LDSM_X4(fah[nxt][mi], ahB + off);
                    LDSM_X4(fal[nxt][mi], alB + off);
                }
                #pragma unroll
                for (int ni = 0; ni < 2; ++ni) {
                    uint32_t off = (uint32_t)(bRow + ni * 16) * ROWB2 + kbyte + bSeg;
                    uint32_t r[4];
                    LDSM_X4(r, phB + off);
                    fbh[nxt][2 * ni][0] = r[0]; fbh[nxt][2 * ni][1] = r[1];
                    fbh[nxt][2 * ni + 1][0] = r[2]; fbh[nxt][2 * ni + 1][1] = r[3];
                    LDSM_X4(r, plB + off);
                    fbl[nxt][2 * ni][0] = r[0]; fbl[nxt][2 * ni][1] = r[1];
                    fbl[nxt][2 * ni + 1][0] = r[2]; fbl[nxt][2 * ni + 1][1] = r[3];
                }
            }
            #pragma unroll
            for (int mi = 0; mi < 4; ++mi)
                #pragma unroll
                for (int nf = 0; nf < 4; ++nf) {
                    mma16816(acc[mi][nf], fah[cur][mi], fbh[cur][nf]);  // hi*hi
                    mma16816(acc[mi][nf], fah[cur][mi], fbl[cur][nf]);  // hi*lo
                    mma16816(acc[mi][nf], fal[cur][mi], fbh[cur][nf]);  // lo*hi
                }
        }
        __syncthreads();
    }

    float* Sz = g_S + (size_t)blockIdx.z * QN * CN;
    #pragma unroll
    for (int mi = 0; mi < 4; ++mi) {
        int r0 = bm + wm + mi * 16 + (lane >> 2);
        #pragma unroll
        for (int nf = 0; nf < 4; ++nf) {
            int col = bn + wn + nf * 8 + 2 * (lane & 3);
            float2 v0 = {acc[mi][nf][0], acc[mi][nf][1]};
            float2 v1 = {acc[mi][nf][2], acc[mi][nf][3]};
            *(float2*)&Sz[(size_t)r0 * CN + col]       = v0;
            *(float2*)&Sz[(size_t)(r0 + 8) * CN + col] = v1;
        }
    }
}

// ---------------------------------------------------------------------------
// Final max over lags
// ---------------------------------------------------------------------------
__global__ void maxlag_kernel(float* __restrict__ out) {
    int idx = blockIdx.x * blockDim.x + threadIdx.x;
    float m = g_S[idx];
    #pragma unroll
    for (int j = 1; j < NLAG; ++j)
        m = fmaxf(m, g_S[(size_t)j * QN * CN + idx]);
    out[idx] = m;
}

// ---------------------------------------------------------------------------
// Launch
// ---------------------------------------------------------------------------
extern "C" void kernel_launch(void* const* d_in, const int* in_sizes, int n_in,
                              void* d_out, int out_size) {
    const float* audio = (const float*)d_in[0];
    const float* video = (const float*)d_in[1];
    const float* a_w1  = (const float*)d_in[2];
    const float* a_b1  = (const float*)d_in[3];
    const float* a_w2  = (const float*)d_in[4];
    const float* a_b2  = (const float*)d_in[5];
    const float* v_w1  = (const float*)d_in[6];
    const float* v_b1  = (const float*)d_in[7];
    const float* v_w2  = (const float*)d_in[8];
    const float* v_b2  = (const float*)d_in[9];
    const float* W     = (const float*)d_in[10];
    float* out = (float*)d_out;

    float *gWc, *gbc;
    __nv_bfloat16 *gHh, *gHl, *gAh, *gAl, *gPh, *gPl;
    __nv_bfloat16 *gW1ah, *gW1al, *gW1vh, *gW1vl, *gW2ah, *gW2al, *gWcth, *gWctl;
    cudaGetSymbolAddress((void**)&gHh, g_Hh);
    cudaGetSymbolAddress((void**)&gHl, g_Hl);
    cudaGetSymbolAddress((void**)&gAh, g_Ah);
    cudaGetSymbolAddress((void**)&gAl, g_Al);
    cudaGetSymbolAddress((void**)&gPh, g_Ph);
    cudaGetSymbolAddress((void**)&gPl, g_Pl);
    cudaGetSymbolAddress((void**)&gWc, g_Wc);
    cudaGetSymbolAddress((void**)&gbc, g_bc);
    cudaGetSymbolAddress((void**)&gW1ah, g_W1ah);
    cudaGetSymbolAddress((void**)&gW1al, g_W1al);
    cudaGetSymbolAddress((void**)&gW1vh, g_W1vh);
    cudaGetSymbolAddress((void**)&gW1vl, g_W1vl);
    cudaGetSymbolAddress((void**)&gW2ah, g_W2ah);
    cudaGetSymbolAddress((void**)&gW2al, g_W2al);
    cudaGetSymbolAddress((void**)&gWcth, g_Wcth);
    cudaGetSymbolAddress((void**)&gWctl, g_Wctl);

    cudaFuncSetAttribute(corr_hmma_kernel,
                         cudaFuncAttributeMaxDynamicSharedMemorySize, CORR_SMEM);
    cudaFuncSetAttribute(mlp_hmma_kernel<true, true>,
                         cudaFuncAttributeMaxDynamicSharedMemorySize, HMMA_SMEM);
    cudaFuncSetAttribute(mlp_hmma_kernel<false, false>,
                         cudaFuncAttributeMaxDynamicSharedMemorySize, HMMA_SMEM);

    // 0) prep: fold Wc, split+transpose all weights
    prep_w_kernel<<<DHD, DHD>>>(v_w2, v_b2, W);
    split_t_kernel<<<DHD, 256>>>(a_w1, gW1ah, gW1al, DIN);
    split_t_kernel<<<DHD, 256>>>(v_w1, gW1vh, gW1vl, DIN);
    split_t_kernel<<<DHD, 256>>>(a_w2, gW2ah, gW2al, DHD);
    split_t_kernel<<<DHD, 256>>>(gWc,  gWcth, gWctl, DHD);

    const dim3 mlp_grid(MROWS / 128, DHD / 128);   // 512 x 2

    // 1) audio MLP on HMMA
    mlp_hmma_kernel<true,  true ><<<mlp_grid, 256, HMMA_SMEM>>>(
        audio, nullptr, nullptr, gW1ah, gW1al, a_b1, gHh, gHl, DIN);
    mlp_hmma_kernel<false, false><<<mlp_grid, 256, HMMA_SMEM>>>(
        nullptr, gHh, gHl, gW2ah, gW2al, a_b2, gAh, gAl, DHD);

    // 2) video MLP + folded projection on HMMA
    mlp_hmma_kernel<true,  true ><<<mlp_grid, 256, HMMA_SMEM>>>(
        video, nullptr, nullptr, gW1vh, gW1vl, v_b1, gHh, gHl, DIN);
    mlp_hmma_kernel<false, false><<<mlp_grid, 256, HMMA_SMEM>>>(
        nullptr, gHh, gHl, gWcth, gWctl, gbc, gPh, gPl, DHD);

    // 3) per-lag correlation on HMMA v2 (144 CTAs, one wave)
    corr_hmma_kernel<<<dim3(QN / 128, CN / 128, NLAG), 256, CORR_SMEM>>>(
        gAh, gAl, gPh, gPl);

    // 4) max over lags
    maxlag_kernel<<<(QN * CN) / 256, 256>>>(out);
}